// round 14
// baseline (speedup 1.0000x reference)
#include <cuda_runtime.h>

#define T_STEPS 2048
#define OUT_DIM 8
#define BATCH 512
#define NB 2

typedef unsigned long long ull;

// ---- packed fp32x2 helpers (sm_100+) ----
__device__ __forceinline__ void fma2(ull &d, ull a, ull b) {
    asm("fma.rn.f32x2 %0, %1, %2, %0;" : "+l"(d) : "l"(a), "l"(b));
}
__device__ __forceinline__ ull add2(ull a, ull b) {
    ull r; asm("add.rn.f32x2 %0, %1, %2;" : "=l"(r) : "l"(a), "l"(b)); return r;
}
__device__ __forceinline__ float red2(ull a) {
    float lo, hi;
    asm("mov.b64 {%0,%1}, %2;" : "=f"(lo), "=f"(hi) : "l"(a));
    return lo + hi;
}
__device__ __forceinline__ void lds2(ull &a, ull &b, unsigned addr) {
    asm volatile("ld.shared.v2.b64 {%0,%1}, [%2];" : "=l"(a), "=l"(b) : "r"(addr));
}

// tanh via exp; clamp high side so e stays finite (tanh(15)==1 in fp32)
__device__ __forceinline__ float tanh_(float x) {
    float e = __expf(2.0f * fminf(x, 15.0f));
    return __fdividef(e - 1.0f, e + 1.0f);
}

// 32-wide dot: register row (16 ull) . smem vector, two accumulators
__device__ __forceinline__ void dot32(const ull *__restrict__ w, unsigned saddr,
                                      ull &a0, ull &a1) {
#pragma unroll
    for (int i = 0; i < 4; i++) {
        ull p0, p1, p2, p3;
        lds2(p0, p1, saddr + (unsigned)(i * 32));
        lds2(p2, p3, saddr + (unsigned)(i * 32 + 16));
        fma2(a0, w[4 * i + 0], p0); fma2(a1, w[4 * i + 1], p1);
        fma2(a0, w[4 * i + 2], p2); fma2(a1, w[4 * i + 3], p3);
    }
}

// =====================================================================
// Single fused kernel: 128 threads = 2 batch elements (weights shared).
// lane j: gate=j&3 (i,f,g,o), unit=j>>2, row r=gate*32+u.
// xg computed in-kernel one step ahead (no separate prepass).
// 2 __syncthreads per step; h double-buffered; x double-buffered.
// Activations branchless: sigm(x)=0.5*tanh(0.5x)+0.5.
// =====================================================================
__global__ void __launch_bounds__(128, 2) lstm_fused(
    const float *__restrict__ X,
    const float *__restrict__ Wih0, const float *__restrict__ Whh0,
    const float *__restrict__ bih0, const float *__restrict__ bhh0,
    const float *__restrict__ Wih1, const float *__restrict__ Whh1,
    const float *__restrict__ bih1, const float *__restrict__ bhh1,
    const float *__restrict__ Wfc, const float *__restrict__ bfc,
    float *__restrict__ out)
{
    __shared__ __align__(16) float xs[NB][2][32];   // x double buffer
    __shared__ __align__(16) float h1s[NB][2][32];
    __shared__ __align__(16) float h2s[NB][2][32];

    const int j = threadIdx.x;
    const int b0 = blockIdx.x * NB;
    const int gate = j & 3;
    const int u = j >> 2;
    const int r = gate * 32 + u;
    const int lb = (j & 31) & ~3;     // lane base of 4-lane gate group

    // branchless activation constants: act = m*tanh_(s*g) + a
    const float s0 = (gate == 2) ? 1.0f : 0.5f;
    const float m0 = (gate == 2) ? 1.0f : 0.5f;
    const float a0 = (gate == 2) ? 0.0f : 0.5f;

    // ---- register-resident weights: 4 rows x 32 = 64 ull = 128 regs ----
    ull wi0[16], wh0[16], wi1[16], wh1[16];
    {
        const ull *p;
        p = (const ull *)(Wih0 + r * 32);
#pragma unroll
        for (int i = 0; i < 16; i++) wi0[i] = p[i];
        p = (const ull *)(Whh0 + r * 32);
#pragma unroll
        for (int i = 0; i < 16; i++) wh0[i] = p[i];
        p = (const ull *)(Wih1 + r * 32);
#pragma unroll
        for (int i = 0; i < 16; i++) wi1[i] = p[i];
        p = (const ull *)(Whh1 + r * 32);
#pragma unroll
        for (int i = 0; i < 16; i++) wh1[i] = p[i];
    }
    const float b1 = bih0[r] + bhh0[r];
    const float b2 = bih1[r] + bhh1[r];

    // ---- x loader role: threads 0..63 = (batch grp, feat f) ----
    const int grp = j >> 5;           // warp id
    const int f = j & 31;
    const float *xsrc = X + ((size_t)(b0 + (grp & 1)) * T_STEPS) * 32 + f;

    // prologue: x(0),x(1) to smem, x(2) to reg; init h(-1)=0
    float xr = 0.0f;
    if (grp < 2) {
        xs[grp][0][f] = xsrc[0];
        xs[grp][1][f] = xsrc[32];
        xr = xsrc[64];
    }
    if (j < 32) {
        h1s[0][1][j] = 0.0f; h2s[0][1][j] = 0.0f;
        h1s[1][1][j] = 0.0f; h2s[1][1][j] = 0.0f;
    }
    __syncthreads();

    const unsigned xsb = (unsigned)__cvta_generic_to_shared(&xs[0][0][0]);
    const unsigned h1b = (unsigned)__cvta_generic_to_shared(&h1s[0][0][0]);
    const unsigned h2b = (unsigned)__cvta_generic_to_shared(&h2s[0][0][0]);

    // xgc = xg(0) for both batches
    float xgc[NB], xgn[NB];
    float c1[NB] = {0.0f, 0.0f}, c2[NB] = {0.0f, 0.0f};
#pragma unroll
    for (int bb = 0; bb < NB; bb++) {
        ull A0 = 0ull, A1 = 0ull;
        dot32(wi0, xsb + (unsigned)(bb * 256), A0, A1);
        xgc[bb] = red2(add2(A0, A1)) + b1;
    }

#pragma unroll 1
    for (int t = 0; t < T_STEPS; t++) {
        const unsigned pNew = (unsigned)((t & 1) << 7);
        const unsigned pOld = (unsigned)(((t + 1) & 1) << 7);

        // ===== phase 1: layer-1 gates + c1/h1 update; also xg(t+1) =====
#pragma unroll
        for (int bb = 0; bb < NB; bb++) {
            ull A0 = 0ull, A1 = 0ull;
            dot32(wh0, h1b + (unsigned)(bb * 256) + pOld, A0, A1);
            float g = red2(add2(A0, A1)) + xgc[bb];
            float act = fmaf(m0, tanh_(s0 * g), a0);
            float vi = __shfl_sync(0xffffffffu, act, lb + 0);
            float vf = __shfl_sync(0xffffffffu, act, lb + 1);
            float vg = __shfl_sync(0xffffffffu, act, lb + 2);
            float vo = __shfl_sync(0xffffffffu, act, lb + 3);
            c1[bb] = fmaf(vf, c1[bb], vi * vg);
            float h = vo * tanh_(c1[bb]);
            if (gate == 0) h1s[bb][t & 1][u] = h;
            // xg(t+1) from xs[bb][(t+1)&1]
            ull B0 = 0ull, B1 = 0ull;
            dot32(wi0, xsb + (unsigned)(bb * 256) + pOld, B0, B1);
            xgn[bb] = red2(add2(B0, B1)) + b1;
        }
        __syncthreads();   // publish h1(t)

        // ===== phase 2: layer-2 gates + c2/h2 update; x staging =====
#pragma unroll
        for (int bb = 0; bb < NB; bb++) {
            ull A0 = 0ull, A1 = 0ull;
            dot32(wi1, h1b + (unsigned)(bb * 256) + pNew, A0, A1);
            dot32(wh1, h2b + (unsigned)(bb * 256) + pOld, A0, A1);
            float g = red2(add2(A0, A1)) + b2;
            float act = fmaf(m0, tanh_(s0 * g), a0);
            float vi = __shfl_sync(0xffffffffu, act, lb + 0);
            float vf = __shfl_sync(0xffffffffu, act, lb + 1);
            float vg = __shfl_sync(0xffffffffu, act, lb + 2);
            float vo = __shfl_sync(0xffffffffu, act, lb + 3);
            c2[bb] = fmaf(vf, c2[bb], vi * vg);
            float h = vo * tanh_(c2[bb]);
            if (gate == 0) h2s[bb][t & 1][u] = h;
        }
        // store x(t+2) (parity (t+2)&1 == t&1); fetch x(t+3)
        if (grp < 2) {
            xs[grp][t & 1][f] = xr;
            int tf = t + 3; if (tf > T_STEPS - 1) tf = T_STEPS - 1;
            xr = __ldg(xsrc + (size_t)tf * 32);
        }
        __syncthreads();   // publish h2(t) + staged x

        xgc[0] = xgn[0]; xgc[1] = xgn[1];
    }

    // ===== FC head on h2(T-1): t=2047 -> parity 1 =====
    {
        const int bb = j >> 6;        // 0 or 1
        const int jo = j & 63;
        if (jo < OUT_DIM) {
            float s = bfc[jo];
            const float *wf = Wfc + jo * 32;
#pragma unroll
            for (int k = 0; k < 32; k++) s = fmaf(wf[k], h2s[bb][1][k], s);
            out[(b0 + bb) * OUT_DIM + jo] = s;
        }
    }
}

extern "C" void kernel_launch(void* const* d_in, const int* in_sizes, int n_in,
                              void* d_out, int out_size) {
    (void)in_sizes; (void)n_in; (void)out_size;
    lstm_fused<<<BATCH / NB, 128>>>(
        (const float *)d_in[0],
        (const float *)d_in[1], (const float *)d_in[2],
        (const float *)d_in[3], (const float *)d_in[4],
        (const float *)d_in[5], (const float *)d_in[6],
        (const float *)d_in[7], (const float *)d_in[8],
        (const float *)d_in[9], (const float *)d_in[10],
        (float *)d_out);
}

// round 15
// speedup vs baseline: 2.0799x; 2.0799x over previous
#include <cuda_runtime.h>

#define T_STEPS 2048
#define OUT_DIM 8
#define BATCH 512

typedef unsigned long long ull;

// staging for precomputed layer-1 input projection, layout [b][t][unit*4+gate]
__device__ float g_xg[(size_t)BATCH * T_STEPS * 128];

// ---- packed fp32x2 helpers (sm_100+) ----
__device__ __forceinline__ void fma2(ull &d, ull a, ull b) {
    asm("fma.rn.f32x2 %0, %1, %2, %0;" : "+l"(d) : "l"(a), "l"(b));
}
__device__ __forceinline__ ull add2(ull a, ull b) {
    ull r; asm("add.rn.f32x2 %0, %1, %2;" : "=l"(r) : "l"(a), "l"(b)); return r;
}
__device__ __forceinline__ float red2(ull a) {
    float lo, hi;
    asm("mov.b64 {%0,%1}, %2;" : "=f"(lo), "=f"(hi) : "l"(a));
    return lo + hi;
}
__device__ __forceinline__ void lds2(ull &a, ull &b, unsigned addr) {
    asm volatile("ld.shared.v2.b64 {%0,%1}, [%2];" : "=l"(a), "=l"(b) : "r"(addr));
}

// ---- fast activations via hardware tanh (sm_75+: single MUFU op) ----
__device__ __forceinline__ float tanha(float x) {
    float r; asm("tanh.approx.f32 %0, %1;" : "=f"(r) : "f"(x)); return r;
}
__device__ __forceinline__ float sigm(float x) {
    return fmaf(0.5f, tanha(0.5f * x), 0.5f);
}

// dot of a register-resident 32-wide row (16 packed pairs) with a 32-float smem
// vector; all lanes read the SAME smem address -> broadcast, conflict-free.
__device__ __forceinline__ void dot32(const ull *__restrict__ w, unsigned saddr,
                                      ull &a0, ull &a1, ull &a2, ull &a3) {
#pragma unroll
    for (int i = 0; i < 4; i++) {
        ull p0, p1, p2, p3;
        lds2(p0, p1, saddr + i * 32);
        lds2(p2, p3, saddr + i * 32 + 16);
        fma2(a0, w[4 * i + 0], p0);
        fma2(a1, w[4 * i + 1], p1);
        fma2(a2, w[4 * i + 2], p2);
        fma2(a3, w[4 * i + 3], p3);
    }
}

// =====================================================================
// prepass: g_xg[b][t][ch] = (bih0+bhh0)[r] + Wih0[r,:].x[b,t,:],
//          r = (ch&3)*32 + (ch>>2)   (ch = 4*unit + gate)
// grid (8, 512): blockIdx.x = 256-timestep tile, blockIdx.y = batch.
// block 128: thread j owns channel j. 4096 CTAs -> issue/DRAM saturated.
// =====================================================================
__global__ void __launch_bounds__(128) xg_prepass(
    const float *__restrict__ X, const float *__restrict__ Wih0,
    const float *__restrict__ bih0, const float *__restrict__ bhh0)
{
    __shared__ __align__(16) float xt[32 * 32];   // 32 timesteps x 32 features
    const int j = threadIdx.x;
    const int b = blockIdx.y;
    const int t0 = blockIdx.x * 256;
    const int r = (j & 3) * 32 + (j >> 2);

    ull w[16];
    {
        const ull *p = (const ull *)(Wih0 + r * 32);
#pragma unroll
        for (int i = 0; i < 16; i++) w[i] = p[i];
    }
    const float bias = bih0[r] + bhh0[r];

    const float *xb = X + ((size_t)b * T_STEPS + t0) * 32;
    float *outp = g_xg + ((size_t)b * T_STEPS + t0) * 128;
    const unsigned xtb = (unsigned)__cvta_generic_to_shared(xt);

    for (int tt = 0; tt < 256; tt += 32) {
        __syncthreads();
        const float4 *src = (const float4 *)(xb + tt * 32);
        float4 *dst4 = (float4 *)xt;
        dst4[j] = src[j];
        dst4[j + 128] = src[j + 128];
        __syncthreads();

#pragma unroll 4
        for (int t = 0; t < 32; t++) {
            ull a0 = 0ull, a1 = 0ull;
#pragma unroll
            for (int i = 0; i < 4; i++) {
                ull p0, p1, p2, p3;
                lds2(p0, p1, xtb + (unsigned)(t * 128 + i * 32));
                lds2(p2, p3, xtb + (unsigned)(t * 128 + i * 32 + 16));
                fma2(a0, w[4 * i + 0], p0); fma2(a1, w[4 * i + 1], p1);
                fma2(a0, w[4 * i + 2], p2); fma2(a1, w[4 * i + 3], p3);
            }
            outp[(size_t)(tt + t) * 128 + j] = red2(add2(a0, a1)) + bias;
        }
    }
}

// =====================================================================
// recurrent kernel (R7 structure, measured fastest): 64 threads = 1 batch.
// warp 0: gate rows {i,f}; warp 1: {g,o}. 2 rows/lane, both layers.
// 3 tiny 2-warp barriers per step; smem gate exchange; h double-buffered
// via xb ping-pong. ONLY change vs R7: tanh.approx activations.
// =====================================================================
__global__ void __launch_bounds__(64, 4) lstm_rec(
    const float *__restrict__ Whh0,
    const float *__restrict__ Wih1, const float *__restrict__ Whh1,
    const float *__restrict__ bih1, const float *__restrict__ bhh1,
    const float *__restrict__ Wfc, const float *__restrict__ bfc,
    float *__restrict__ out)
{
    __shared__ __align__(16) float h1s[32];
    __shared__ __align__(16) float h2s[32];
    __shared__ __align__(16) float xb0[32];
    __shared__ __align__(16) float xb1[32];

    const int tid = threadIdx.x;
    const int b = blockIdx.x;
    const int w = tid >> 5;           // 0: gates i,f   1: gates g,o
    const int u = tid & 31;           // hidden unit
    const int rA = (2 * w) * 32 + u;  // first owned gate row
    const int rB = rA + 32;           // second owned gate row

    // ---- register-resident weights: 6 rows x 32 = 96 ull = 192 regs ----
    ull wh0A[16], wh0B[16], wi1A[16], wi1B[16], wh1A[16], wh1B[16];
    {
        const ull *p;
        p = (const ull *)(Whh0 + rA * 32);
#pragma unroll
        for (int i = 0; i < 16; i++) wh0A[i] = p[i];
        p = (const ull *)(Whh0 + rB * 32);
#pragma unroll
        for (int i = 0; i < 16; i++) wh0B[i] = p[i];
        p = (const ull *)(Wih1 + rA * 32);
#pragma unroll
        for (int i = 0; i < 16; i++) wi1A[i] = p[i];
        p = (const ull *)(Wih1 + rB * 32);
#pragma unroll
        for (int i = 0; i < 16; i++) wi1B[i] = p[i];
        p = (const ull *)(Whh1 + rA * 32);
#pragma unroll
        for (int i = 0; i < 16; i++) wh1A[i] = p[i];
        p = (const ull *)(Whh1 + rB * 32);
#pragma unroll
        for (int i = 0; i < 16; i++) wh1B[i] = p[i];
    }
    const float b2A = bih1[rA] + bhh1[rA];
    const float b2B = bih1[rB] + bhh1[rB];

    // xg stream: float4 per (t, u) covering channels 4u..4u+3
    const float4 *xgp = (const float4 *)(g_xg + (size_t)b * T_STEPS * 128) + u;
    float4 cur = __ldg(xgp);
    float4 nxt = __ldg(xgp + 32);

    if (tid < 32) { h1s[tid] = 0.0f; h2s[tid] = 0.0f; }
    float c = 0.0f;                   // warp0: c1   warp1: c2

    const unsigned h1b = (unsigned)__cvta_generic_to_shared(h1s);
    const unsigned h2b = (unsigned)__cvta_generic_to_shared(h2s);
    __syncthreads();

#pragma unroll 1
    for (int t = 0; t < T_STEPS; t++) {
        // prefetch xg(t+2)
        float4 pre;
        {
            int tf = t + 2; if (tf > T_STEPS - 1) tf = T_STEPS - 1;
            pre = __ldg(xgp + (size_t)tf * 32);
        }

        // ===== phase A: layer-1 gates (rows rA,rB over h1(t-1)) =====
        ull a0 = 0ull, a1 = 0ull, d0 = 0ull, d1 = 0ull;
#pragma unroll
        for (int i = 0; i < 4; i++) {
            ull p0, p1, p2, p3;
            lds2(p0, p1, h1b + (unsigned)(i * 32));
            lds2(p2, p3, h1b + (unsigned)(i * 32 + 16));
            fma2(a0, wh0A[4 * i + 0], p0); fma2(a1, wh0A[4 * i + 1], p1);
            fma2(a0, wh0A[4 * i + 2], p2); fma2(a1, wh0A[4 * i + 3], p3);
            fma2(d0, wh0B[4 * i + 0], p0); fma2(d1, wh0B[4 * i + 1], p1);
            fma2(d0, wh0B[4 * i + 2], p2); fma2(d1, wh0B[4 * i + 3], p3);
        }
        float g0 = red2(add2(a0, a1)) + (w ? cur.z : cur.x);
        float g1 = red2(add2(d0, d1)) + (w ? cur.w : cur.y);
        float act0 = w ? tanha(g0) : sigm(g0);   // w0: i     w1: g
        float act1 = sigm(g1);                   // w0: f     w1: o
        if (w) { xb0[u] = act0; xb1[u] = act1; }
        __syncthreads();                         // bar 1

        // ===== phase B (warp 0): c1/h1 update =====
        if (!w) {
            float vg = xb0[u], vo = xb1[u];
            c = fmaf(act1, c, act0 * vg);        // c1 = f*c1 + i*g
            h1s[u] = vo * tanha(c);
        }
        __syncthreads();                         // bar 2

        // ===== phase C: layer-2 gates (rows rA,rB over [h1(t) | h2(t-1)]) =====
        a0 = 0ull; a1 = 0ull; d0 = 0ull; d1 = 0ull;
#pragma unroll
        for (int i = 0; i < 4; i++) {
            ull p0, p1, p2, p3;
            lds2(p0, p1, h1b + (unsigned)(i * 32));
            lds2(p2, p3, h1b + (unsigned)(i * 32 + 16));
            fma2(a0, wi1A[4 * i + 0], p0); fma2(a1, wi1A[4 * i + 1], p1);
            fma2(a0, wi1A[4 * i + 2], p2); fma2(a1, wi1A[4 * i + 3], p3);
            fma2(d0, wi1B[4 * i + 0], p0); fma2(d1, wi1B[4 * i + 1], p1);
            fma2(d0, wi1B[4 * i + 2], p2); fma2(d1, wi1B[4 * i + 3], p3);
        }
#pragma unroll
        for (int i = 0; i < 4; i++) {
            ull p0, p1, p2, p3;
            lds2(p0, p1, h2b + (unsigned)(i * 32));
            lds2(p2, p3, h2b + (unsigned)(i * 32 + 16));
            fma2(a0, wh1A[4 * i + 0], p0); fma2(a1, wh1A[4 * i + 1], p1);
            fma2(a0, wh1A[4 * i + 2], p2); fma2(a1, wh1A[4 * i + 3], p3);
            fma2(d0, wh1B[4 * i + 0], p0); fma2(d1, wh1B[4 * i + 1], p1);
            fma2(d0, wh1B[4 * i + 2], p2); fma2(d1, wh1B[4 * i + 3], p3);
        }
        g0 = red2(add2(a0, a1)) + b2A;
        g1 = red2(add2(d0, d1)) + b2B;
        act0 = w ? tanha(g0) : sigm(g0);
        act1 = sigm(g1);
        if (!w) { xb0[u] = act0; xb1[u] = act1; }
        __syncthreads();                         // bar 3

        // ===== phase D (warp 1): c2/h2 update =====
        if (w) {
            float vi = xb0[u], vf = xb1[u];
            c = fmaf(vf, c, vi * act0);          // c2 = f*c2 + i*g
            h2s[u] = act1 * tanha(c);
        }
        // next step's bar 1 makes h2s/xb visible before their next use

        cur = nxt; nxt = pre;
    }
    __syncthreads();

    // ===== FC head on h2(T-1) =====
    if (tid < OUT_DIM) {
        float s = bfc[tid];
        const float *wf = Wfc + tid * 32;
#pragma unroll
        for (int k = 0; k < 32; k++) s = fmaf(wf[k], h2s[k], s);
        out[b * OUT_DIM + tid] = s;
    }
}

extern "C" void kernel_launch(void* const* d_in, const int* in_sizes, int n_in,
                              void* d_out, int out_size) {
    (void)in_sizes; (void)n_in; (void)out_size;
    const float *X    = (const float *)d_in[0];
    const float *Wih0 = (const float *)d_in[1];
    const float *Whh0 = (const float *)d_in[2];
    const float *bih0 = (const float *)d_in[3];
    const float *bhh0 = (const float *)d_in[4];
    const float *Wih1 = (const float *)d_in[5];
    const float *Whh1 = (const float *)d_in[6];
    const float *bih1 = (const float *)d_in[7];
    const float *bhh1 = (const float *)d_in[8];
    const float *Wfc  = (const float *)d_in[9];
    const float *bfc  = (const float *)d_in[10];

    dim3 pg(8, BATCH);
    xg_prepass<<<pg, 128>>>(X, Wih0, bih0, bhh0);
    lstm_rec<<<BATCH, 64>>>(Whh0, Wih1, Whh1, bih1, bhh1, Wfc, bfc,
                            (float *)d_out);
}